// round 6
// baseline (speedup 1.0000x reference)
#include <cuda_runtime.h>
#include <cuda_bf16.h>
#include <cstdint>

#define N_TOKENS 8192
#define D_MODEL  1024
#define D_FF     4096
#define N_EXPERTS 8

#define BM 128
#define BN 128
#define BK 64
#define NKSTAGE (D_MODEL / BK)        // 16
#define PIPE 4
#define MAX_TILES 72
#define PAD_ROWS (N_TOKENS + N_EXPERTS * BM)   // 9216
#define QSCALE 32512.0f               // 127*256

// ---------------- scratch ----------------
__device__ int g_top1[N_TOKENS];
__device__ int g_counts[N_EXPERTS];
__device__ int g_cursor[N_EXPERTS];
__device__ int g_offsets[N_EXPERTS];
__device__ int g_order[PAD_ROWS];              // -1 = pad row
__device__ int g_tile_expert[MAX_TILES + 8];
__device__ int g_tile_row[MAX_TILES + 8];
__device__ int g_ntiles;

__device__ char  g_xq_hi[(size_t)PAD_ROWS * D_MODEL];
__device__ char  g_xq_lo[(size_t)PAD_ROWS * D_MODEL];
__device__ float g_xscale[PAD_ROWS];
__device__ char  g_wq_hi[(size_t)N_EXPERTS * D_FF * D_MODEL];   // W^T [e][f][d]
__device__ char  g_wq_lo[(size_t)N_EXPERTS * D_FF * D_MODEL];
__device__ float g_wscale[N_EXPERTS * D_FF];

// ---------------- helpers ----------------
__device__ __forceinline__ uint32_t smem_u32(const void* p) {
    uint32_t a;
    asm("{ .reg .u64 t; cvta.to.shared.u64 t, %1; cvt.u32.u64 %0, t; }" : "=r"(a) : "l"(p));
    return a;
}
__device__ __forceinline__ void cp16(uint32_t dst, const void* src) {
    asm volatile("cp.async.cg.shared.global [%0], [%1], 16;\n" :: "r"(dst), "l"(src));
}
__device__ __forceinline__ void cp_commit() { asm volatile("cp.async.commit_group;\n" ::: "memory"); }
template <int N> __device__ __forceinline__ void cp_wait() {
    asm volatile("cp.async.wait_group %0;\n" :: "n"(N) : "memory");
}
__device__ __forceinline__ void ldsm4(uint32_t r[4], uint32_t addr) {
    asm volatile("ldmatrix.sync.aligned.m8n8.x4.shared.b16 {%0,%1,%2,%3}, [%4];"
                 : "=r"(r[0]), "=r"(r[1]), "=r"(r[2]), "=r"(r[3]) : "r"(addr));
}
// int8 MMA: D(s32) += A(s8,16x32) * B(s8,32x8)
#define IMMA(d, a, b0, b1)                                                         \
    asm volatile("mma.sync.aligned.m16n8k32.row.col.s32.s8.s8.s32 "                \
                 "{%0,%1,%2,%3},{%4,%5,%6,%7},{%8,%9},{%0,%1,%2,%3};"              \
                 : "+r"((d)[0]), "+r"((d)[1]), "+r"((d)[2]), "+r"((d)[3])          \
                 : "r"((a)[0]), "r"((a)[1]), "r"((a)[2]), "r"((a)[3]),             \
                   "r"(b0), "r"(b1))

// smem tile rows of 64B = 4 x 16B chunks, chunk ^= (row>>1)&3  (conflict-free)
__device__ __forceinline__ uint32_t swz(int row, int c) {
    return (uint32_t)(row * 64 + ((c ^ ((row >> 1) & 3)) << 4));
}

#define A_HI 0
#define A_LO 8192
#define B_HI 16384
#define B_LO 24576
#define STAGE_BYTES 32768
#define SMEM_TOTAL (PIPE * STAGE_BYTES)   // 131072

// ---------------- gate path ----------------
__global__ void k_init() {
    int i = blockIdx.x * blockDim.x + threadIdx.x;
    if (i < N_EXPERTS) { g_counts[i] = 0; g_cursor[i] = 0; }
    if (i < PAD_ROWS) g_order[i] = -1;
}

__global__ void k_gate(const float* __restrict__ x, const float* __restrict__ gw,
                       const float* __restrict__ gb) {
    int warp = (blockIdx.x * blockDim.x + threadIdx.x) >> 5;
    int lane = threadIdx.x & 31;
    if (warp >= N_TOKENS) return;
    const float* xr = x + (size_t)warp * D_MODEL;
    float acc[N_EXPERTS];
#pragma unroll
    for (int e = 0; e < N_EXPERTS; e++) acc[e] = 0.f;
#pragma unroll 4
    for (int i = 0; i < D_MODEL / 32; i++) {
        int d = i * 32 + lane;
        float xv = xr[d];
        const float* g = gw + d * N_EXPERTS;
#pragma unroll
        for (int e = 0; e < N_EXPERTS; e++) acc[e] += xv * g[e];
    }
#pragma unroll
    for (int e = 0; e < N_EXPERTS; e++)
#pragma unroll
        for (int off = 16; off; off >>= 1)
            acc[e] += __shfl_xor_sync(0xffffffffu, acc[e], off);
    if (lane == 0) {
        int best = 0;
        float bv = acc[0] + gb[0];
#pragma unroll
        for (int e = 1; e < N_EXPERTS; e++) {
            float v = acc[e] + gb[e];
            if (v > bv) { bv = v; best = e; }   // first max wins == jnp.argmax
        }
        g_top1[warp] = best;
        atomicAdd(&g_counts[best], 1);
    }
}

__global__ void k_scan() {
    int base = 0, nt = 0;
    for (int e = 0; e < N_EXPERTS; e++) {
        g_offsets[e] = base;
        int c = g_counts[e];
        int t = (c + BM - 1) / BM;
        for (int r = 0; r < t; r++) {
            g_tile_expert[nt] = e;
            g_tile_row[nt] = base + r * BM;
            nt++;
        }
        base += t * BM;
    }
    g_ntiles = nt;
}

__global__ void k_scatter() {
    int n = blockIdx.x * blockDim.x + threadIdx.x;
    if (n >= N_TOKENS) return;
    int e = g_top1[n];
    int pos = g_offsets[e] + atomicAdd(&g_cursor[e], 1);
    g_order[pos] = n;
}

// ---------------- quantization ----------------
__device__ __forceinline__ void q_split(float X, char& hi, char& lo) {
    float h = rintf(X * (1.0f / 256.0f));
    h = fminf(fmaxf(h, -127.f), 127.f);
    float r = X - 256.f * h;
    float l = fminf(fmaxf(rintf(r), -127.f), 127.f);
    hi = (char)(int)h;
    lo = (char)(int)l;
}

// gather token row into grouped/padded position + 2-way int8 split
__global__ void k_quant_x(const float* __restrict__ x) {
    int pos = blockIdx.x;
    int tok = g_order[pos];
    int t = threadIdx.x;       // 256
    float f[4] = {0.f, 0.f, 0.f, 0.f};
    if (tok >= 0) {
        float4 v = *(const float4*)(x + (size_t)tok * D_MODEL + t * 4);
        f[0] = v.x; f[1] = v.y; f[2] = v.z; f[3] = v.w;
    }
    float m = fmaxf(fmaxf(fabsf(f[0]), fabsf(f[1])), fmaxf(fabsf(f[2]), fabsf(f[3])));
#pragma unroll
    for (int off = 16; off; off >>= 1)
        m = fmaxf(m, __shfl_xor_sync(0xffffffffu, m, off));
    __shared__ float red[8];
    if ((t & 31) == 0) red[t >> 5] = m;
    __syncthreads();
    if (t == 0) {
        float M = red[0];
#pragma unroll
        for (int i = 1; i < 8; i++) M = fmaxf(M, red[i]);
        red[0] = fmaxf(M, 1e-20f);
        g_xscale[pos] = red[0] * (1.0f / QSCALE);
    }
    __syncthreads();
    float inv = QSCALE / red[0];
    char h[4], l[4];
#pragma unroll
    for (int j = 0; j < 4; j++) q_split(f[j] * inv, h[j], l[j]);
    size_t o = (size_t)pos * D_MODEL + t * 4;
    *(uint32_t*)(g_xq_hi + o) = *(uint32_t*)h;
    *(uint32_t*)(g_xq_lo + o) = *(uint32_t*)l;
}

// per-[e][f] column max of |W|
__global__ void k_wmax(const float* __restrict__ ew) {
    int e = blockIdx.x;
    int f = blockIdx.y * 512 + threadIdx.x;
    const float* W = ew + (size_t)e * D_MODEL * D_FF + f;
    float m = 0.f;
#pragma unroll 4
    for (int d = 0; d < D_MODEL; d++)
        m = fmaxf(m, fabsf(W[(size_t)d * D_FF]));
    g_wscale[e * D_FF + f] = fmaxf(m, 1e-20f) * (1.0f / QSCALE);
}

// transpose W[e][d][f] -> W^T[e][f][d] + int8 split
__global__ void k_wquant(const float* __restrict__ ew) {
    __shared__ float ts[32][33];
    int e = blockIdx.z;
    int f0 = blockIdx.x * 32;
    int d0 = blockIdx.y * 32;
    int c = threadIdx.x & 31;
    int r0 = threadIdx.x >> 5;
    const float* W = ew + (size_t)e * D_MODEL * D_FF;
#pragma unroll
    for (int r = r0; r < 32; r += 8)
        ts[r][c] = W[(size_t)(d0 + r) * D_FF + f0 + c];
    __syncthreads();
#pragma unroll
    for (int r = r0; r < 32; r += 8) {
        float v = ts[c][r];                     // = W[d0+c][f0+r]
        float inv = 1.0f / g_wscale[e * D_FF + f0 + r];
        char h, l;
        q_split(v * inv, h, l);
        size_t o = ((size_t)e * D_FF + f0 + r) * D_MODEL + d0 + c;
        g_wq_hi[o] = h;
        g_wq_lo[o] = l;
    }
}

// ---------------- int8 grouped GEMM ----------------
__device__ __forceinline__ void issue_stage(int tid, uint32_t sb, int stage,
                                            int row0, size_t wbase, int k0) {
    uint32_t base = sb + (stage % PIPE) * STAGE_BYTES;
    // 2048 cp16 total: 0-511 A_HI, 512-1023 A_LO, 1024-1535 B_HI, 1536-2047 B_LO
#pragma unroll
    for (int i = 0; i < 4; i++) {
        int idx = tid + i * 512;
        int sect = idx >> 9;           // 0..3
        int rem = idx & 511;
        int row = rem >> 2, c = rem & 3;
        uint32_t so = swz(row, c);
        const char* src;
        uint32_t dst;
        if (sect == 0)      { src = g_xq_hi + (size_t)(row0 + row) * D_MODEL + k0 + c * 16; dst = base + A_HI + so; }
        else if (sect == 1) { src = g_xq_lo + (size_t)(row0 + row) * D_MODEL + k0 + c * 16; dst = base + A_LO + so; }
        else if (sect == 2) { src = g_wq_hi + wbase + (size_t)row * D_MODEL + k0 + c * 16;  dst = base + B_HI + so; }
        else                { src = g_wq_lo + wbase + (size_t)row * D_MODEL + k0 + c * 16;  dst = base + B_LO + so; }
        cp16(dst, src);
    }
    cp_commit();
}

__global__ void __launch_bounds__(512, 1)
k_gemm(const float* __restrict__ eb, float* __restrict__ out) {
    int tile = blockIdx.x;
    if (tile >= g_ntiles) return;
    int e = g_tile_expert[tile];
    int row0 = g_tile_row[tile];
    int col0 = blockIdx.y * BN;

    extern __shared__ char smem[];
    __shared__ int s_tok[BM];
    uint32_t sb = smem_u32(smem);
    int tid = threadIdx.x;
    int lane = tid & 31;
    int wid = tid >> 5;
    int wm = wid & 3;        // 4 M groups of 32 rows
    int wn = wid >> 2;       // 4 N groups of 32 cols

    for (int m = tid; m < BM; m += 512) s_tok[m] = g_order[row0 + m];

    size_t wbase = ((size_t)e * D_FF + col0) * D_MODEL;

    int acc1[2][4][4];       // hh      (weight 65536)
    int acc2[2][4][4];       // hl + lh (weight 256)
#pragma unroll
    for (int a = 0; a < 2; a++)
#pragma unroll
        for (int b = 0; b < 4; b++)
#pragma unroll
            for (int c = 0; c < 4; c++) { acc1[a][b][c] = 0; acc2[a][b][c] = 0; }

#pragma unroll
    for (int p = 0; p < PIPE - 1; p++) issue_stage(tid, sb, p, row0, wbase, p * BK);

    // ldmatrix lane addressing
    int a_row = wm * 32 + (lane & 7) + ((lane >> 3) & 1) * 8;   // + mf*16
    int a_c   = (lane >> 4) & 1;                                // + 2*ks
    int b_row = wn * 32 + (lane & 7) + ((lane >> 4) & 1) * 8;   // + pair*16
    int b_c   = (lane >> 3) & 1;                                // + 2*ks

    for (int s = 0; s < NKSTAGE; s++) {
        cp_wait<PIPE - 2>();
        __syncthreads();
        if (s + PIPE - 1 < NKSTAGE)
            issue_stage(tid, sb, s + PIPE - 1, row0, wbase, (s + PIPE - 1) * BK);
        else
            cp_commit();   // keep wait_group accounting aligned

        uint32_t base = sb + (s % PIPE) * STAGE_BYTES;

#pragma unroll
        for (int ks = 0; ks < 2; ks++) {
            uint32_t ah[2][4], al[2][4];
#pragma unroll
            for (int mf = 0; mf < 2; mf++) {
                uint32_t so = swz(a_row + mf * 16, 2 * ks + a_c);
                ldsm4(ah[mf], base + A_HI + so);
                ldsm4(al[mf], base + A_LO + so);
            }
            uint32_t bh[2][4], bl[2][4];
#pragma unroll
            for (int p = 0; p < 2; p++) {
                uint32_t so = swz(b_row + p * 16, 2 * ks + b_c);
                ldsm4(bh[p], base + B_HI + so);
                ldsm4(bl[p], base + B_LO + so);
            }
            // term hh -> acc1 (8 independent accs)
#pragma unroll
            for (int p = 0; p < 2; p++)
#pragma unroll
                for (int mf = 0; mf < 2; mf++) {
                    IMMA(acc1[mf][2 * p],     ah[mf], bh[p][0], bh[p][1]);
                    IMMA(acc1[mf][2 * p + 1], ah[mf], bh[p][2], bh[p][3]);
                }
            // term hl -> acc2
#pragma unroll
            for (int p = 0; p < 2; p++)
#pragma unroll
                for (int mf = 0; mf < 2; mf++) {
                    IMMA(acc2[mf][2 * p],     ah[mf], bl[p][0], bl[p][1]);
                    IMMA(acc2[mf][2 * p + 1], ah[mf], bl[p][2], bl[p][3]);
                }
            // term lh -> acc2
#pragma unroll
            for (int p = 0; p < 2; p++)
#pragma unroll
                for (int mf = 0; mf < 2; mf++) {
                    IMMA(acc2[mf][2 * p],     al[mf], bh[p][0], bh[p][1]);
                    IMMA(acc2[mf][2 * p + 1], al[mf], bh[p][2], bh[p][3]);
                }
        }
    }
    __syncthreads();

    // epilogue: dequant + bias, scatter rows to tokens
#pragma unroll
    for (int mf = 0; mf < 2; mf++) {
        int r_lo = wm * 32 + mf * 16 + (lane >> 2);
        int r_hi = r_lo + 8;
        int t_lo = s_tok[r_lo];
        int t_hi = s_tok[r_hi];
        float sa_lo = g_xscale[row0 + r_lo];
        float sa_hi = g_xscale[row0 + r_hi];
#pragma unroll
        for (int nf = 0; nf < 4; nf++) {
            int col = col0 + wn * 32 + nf * 8 + (lane & 3) * 2;
            float sb0 = g_wscale[e * D_FF + col];
            float sb1 = g_wscale[e * D_FF + col + 1];
            float b0 = eb[(size_t)e * D_FF + col];
            float b1 = eb[(size_t)e * D_FF + col + 1];
            if (t_lo >= 0) {
                float2 v;
                v.x = sa_lo * sb0 * (65536.f * (float)acc1[mf][nf][0] + 256.f * (float)acc2[mf][nf][0]) + b0;
                v.y = sa_lo * sb1 * (65536.f * (float)acc1[mf][nf][1] + 256.f * (float)acc2[mf][nf][1]) + b1;
                *(float2*)(out + (size_t)t_lo * D_FF + col) = v;
            }
            if (t_hi >= 0) {
                float2 v;
                v.x = sa_hi * sb0 * (65536.f * (float)acc1[mf][nf][2] + 256.f * (float)acc2[mf][nf][2]) + b0;
                v.y = sa_hi * sb1 * (65536.f * (float)acc1[mf][nf][3] + 256.f * (float)acc2[mf][nf][3]) + b1;
                *(float2*)(out + (size_t)t_hi * D_FF + col) = v;
            }
        }
    }
}

extern "C" void kernel_launch(void* const* d_in, const int* in_sizes, int n_in,
                              void* d_out, int out_size) {
    const float* x  = (const float*)d_in[0];
    const float* gw = (const float*)d_in[1];
    const float* gb = (const float*)d_in[2];
    const float* ew = (const float*)d_in[3];
    const float* eb = (const float*)d_in[4];
    float* out = (float*)d_out;

    cudaFuncSetAttribute(k_gemm, cudaFuncAttributeMaxDynamicSharedMemorySize, SMEM_TOTAL);

    k_init<<<(PAD_ROWS + 255) / 256, 256>>>();
    k_gate<<<N_TOKENS / 8, 256>>>(x, gw, gb);
    k_scan<<<1, 1>>>();
    k_scatter<<<N_TOKENS / 256, 256>>>();
    k_quant_x<<<PAD_ROWS, 256>>>(x);
    {
        dim3 g(N_EXPERTS, D_FF / 512);
        k_wmax<<<g, 512>>>(ew);
    }
    {
        dim3 g(D_FF / 32, D_MODEL / 32, N_EXPERTS);
        k_wquant<<<g, 256>>>(ew);
    }
    {
        dim3 g(MAX_TILES, D_FF / BN);
        k_gemm<<<g, 512, SMEM_TOTAL>>>(eb, out);
    }
}

// round 7
// speedup vs baseline: 3.9136x; 3.9136x over previous
#include <cuda_runtime.h>
#include <cuda_fp16.h>
#include <cstdint>

#define N_TOKENS 8192
#define D_MODEL  1024
#define D_FF     4096
#define N_EXPERTS 8

#define BM 128
#define BN 256
#define BK 32
#define NKSTAGE (D_MODEL / BK)        // 32
#define PIPE 4
#define MAX_TILES 72
#define PAD_ROWS (N_TOKENS + N_EXPERTS * BM)   // 9216

// ---------------- scratch ----------------
__device__ int g_top1[N_TOKENS];
__device__ int g_counts[N_EXPERTS];
__device__ int g_cursor[N_EXPERTS];
__device__ int g_offsets[N_EXPERTS];
__device__ int g_order[PAD_ROWS];              // -1 = pad row
__device__ int g_tile_expert[MAX_TILES + 8];
__device__ int g_tile_row[MAX_TILES + 8];
__device__ int g_ntiles;

__device__ __half g_xh[(size_t)PAD_ROWS * D_MODEL];            // grouped+padded, fp16
__device__ __half g_wh[(size_t)N_EXPERTS * D_MODEL * D_FF];    // W hi, layout [e][d][f]
__device__ __half g_wl[(size_t)N_EXPERTS * D_MODEL * D_FF];    // W lo (residual)

// ---------------- helpers ----------------
__device__ __forceinline__ uint32_t smem_u32(const void* p) {
    uint32_t a;
    asm("{ .reg .u64 t; cvta.to.shared.u64 t, %1; cvt.u32.u64 %0, t; }" : "=r"(a) : "l"(p));
    return a;
}
__device__ __forceinline__ void cp16(uint32_t dst, const void* src) {
    asm volatile("cp.async.cg.shared.global [%0], [%1], 16;\n" :: "r"(dst), "l"(src));
}
__device__ __forceinline__ void cp_commit() { asm volatile("cp.async.commit_group;\n" ::: "memory"); }
template <int N> __device__ __forceinline__ void cp_wait() {
    asm volatile("cp.async.wait_group %0;\n" :: "n"(N) : "memory");
}
__device__ __forceinline__ void ldsm4(uint32_t r[4], uint32_t addr) {
    asm volatile("ldmatrix.sync.aligned.m8n8.x4.shared.b16 {%0,%1,%2,%3}, [%4];"
                 : "=r"(r[0]), "=r"(r[1]), "=r"(r[2]), "=r"(r[3]) : "r"(addr));
}
__device__ __forceinline__ void ldsm4t(uint32_t r[4], uint32_t addr) {
    asm volatile("ldmatrix.sync.aligned.m8n8.x4.trans.shared.b16 {%0,%1,%2,%3}, [%4];"
                 : "=r"(r[0]), "=r"(r[1]), "=r"(r[2]), "=r"(r[3]) : "r"(addr));
}
// fp16 MMA, fp32 accumulate
#define MMA(d, a, b0, b1)                                                          \
    asm volatile("mma.sync.aligned.m16n8k16.row.col.f32.f16.f16.f32 "              \
                 "{%0,%1,%2,%3},{%4,%5,%6,%7},{%8,%9},{%0,%1,%2,%3};"              \
                 : "+f"((d)[0]), "+f"((d)[1]), "+f"((d)[2]), "+f"((d)[3])          \
                 : "r"((a)[0]), "r"((a)[1]), "r"((a)[2]), "r"((a)[3]),             \
                   "r"(b0), "r"(b1))

// A tile: 128 rows x 64B (32 fp16), 4x16B chunks, chunk ^= (row>>1)&3  (R3-proven)
__device__ __forceinline__ uint32_t swzA(int row, int c) {
    return (uint32_t)(row * 64 + ((c ^ ((row >> 1) & 3)) << 4));
}
// B tile: 32 k-rows x 512B (256 fp16), 32x16B chunks, chunk ^= row&7
__device__ __forceinline__ uint32_t swzB(int row, int c) {
    return (uint32_t)(row * 512 + ((c ^ (row & 7)) << 4));
}

#define A_OFF 0
#define B_HI  8192
#define B_LO  24576
#define STAGE_BYTES 40960
#define SMEM_TOTAL (PIPE * STAGE_BYTES)   // 163840

// ---------------- gate path ----------------
__global__ void k_init() {
    int i = blockIdx.x * blockDim.x + threadIdx.x;
    if (i < N_EXPERTS) { g_counts[i] = 0; g_cursor[i] = 0; }
    if (i < PAD_ROWS) g_order[i] = -1;
}

__global__ void k_gate(const float* __restrict__ x, const float* __restrict__ gw,
                       const float* __restrict__ gb) {
    int warp = (blockIdx.x * blockDim.x + threadIdx.x) >> 5;
    int lane = threadIdx.x & 31;
    if (warp >= N_TOKENS) return;
    const float* xr = x + (size_t)warp * D_MODEL;
    float acc[N_EXPERTS];
#pragma unroll
    for (int e = 0; e < N_EXPERTS; e++) acc[e] = 0.f;
#pragma unroll 4
    for (int i = 0; i < D_MODEL / 32; i++) {
        int d = i * 32 + lane;
        float xv = xr[d];
        const float* g = gw + d * N_EXPERTS;
#pragma unroll
        for (int e = 0; e < N_EXPERTS; e++) acc[e] += xv * g[e];
    }
#pragma unroll
    for (int e = 0; e < N_EXPERTS; e++)
#pragma unroll
        for (int off = 16; off; off >>= 1)
            acc[e] += __shfl_xor_sync(0xffffffffu, acc[e], off);
    if (lane == 0) {
        int best = 0;
        float bv = acc[0] + gb[0];
#pragma unroll
        for (int e = 1; e < N_EXPERTS; e++) {
            float v = acc[e] + gb[e];
            if (v > bv) { bv = v; best = e; }   // first max wins == jnp.argmax
        }
        g_top1[warp] = best;
        atomicAdd(&g_counts[best], 1);
    }
}

__global__ void k_scan() {
    int base = 0, nt = 0;
    for (int e = 0; e < N_EXPERTS; e++) {
        g_offsets[e] = base;
        int c = g_counts[e];
        int t = (c + BM - 1) / BM;
        for (int r = 0; r < t; r++) {
            g_tile_expert[nt] = e;
            g_tile_row[nt] = base + r * BM;
            nt++;
        }
        base += t * BM;
    }
    g_ntiles = nt;
}

__global__ void k_scatter() {
    int n = blockIdx.x * blockDim.x + threadIdx.x;
    if (n >= N_TOKENS) return;
    int e = g_top1[n];
    int pos = g_offsets[e] + atomicAdd(&g_cursor[e], 1);
    g_order[pos] = n;
}

// ---------------- conversions ----------------
// gather token rows into grouped/padded order, fp32 -> fp16
__global__ void k_half_x(const float* __restrict__ x) {
    int pos = blockIdx.x;
    int tok = g_order[pos];
    int c0 = threadIdx.x * 4;
    __half h[4];
    if (tok >= 0) {
        float4 v = *(const float4*)(x + (size_t)tok * D_MODEL + c0);
        h[0] = __float2half(v.x); h[1] = __float2half(v.y);
        h[2] = __float2half(v.z); h[3] = __float2half(v.w);
    } else {
        h[0] = h[1] = h[2] = h[3] = __float2half(0.f);
    }
    *(uint2*)(g_xh + (size_t)pos * D_MODEL + c0) = *(uint2*)h;
}

// elementwise W -> fp16 hi + fp16 residual (same [e][d][f] layout, NO transpose)
__global__ void k_wsplit(const float* __restrict__ ew) {
    size_t i = ((size_t)blockIdx.x * blockDim.x + threadIdx.x) * 4;
    float4 v = *(const float4*)(ew + i);
    float f[4] = {v.x, v.y, v.z, v.w};
    __half h[4], l[4];
#pragma unroll
    for (int j = 0; j < 4; j++) {
        h[j] = __float2half(f[j]);
        l[j] = __float2half(f[j] - __half2float(h[j]));
    }
    *(uint2*)(g_wh + i) = *(uint2*)h;
    *(uint2*)(g_wl + i) = *(uint2*)l;
}

// ---------------- fp16 2-term grouped GEMM ----------------
__device__ __forceinline__ void issue_stage(int tid, uint32_t sb, int stage,
                                            int row0, int e, int col0, int k0) {
    uint32_t base = sb + (stage % PIPE) * STAGE_BYTES;
    // A: 128 rows x 4 chunks = 512 cp16 (1 per thread)
    {
        int row = tid >> 2, c = tid & 3;
        const __half* src = g_xh + (size_t)(row0 + row) * D_MODEL + k0 + c * 8;
        cp16(base + A_OFF + swzA(row, c), src);
    }
    // B: 32 k-rows x 32 chunks x 2 terms = 2048 cp16 (4 per thread)
#pragma unroll
    for (int i = 0; i < 4; i++) {
        int idx = tid + i * 512;
        int term = idx >> 10, rem = idx & 1023;
        int row = rem >> 5, c = rem & 31;
        const __half* w = term ? g_wl : g_wh;
        const __half* src = w + ((size_t)e * D_MODEL + k0 + row) * D_FF + col0 + c * 8;
        cp16(base + (term ? B_LO : B_HI) + swzB(row, c), src);
    }
    cp_commit();
}

__global__ void __launch_bounds__(512, 1)
k_gemm(const float* __restrict__ eb, float* __restrict__ out) {
    int tile = blockIdx.x;
    if (tile >= g_ntiles) return;
    int e = g_tile_expert[tile];
    int row0 = g_tile_row[tile];
    int col0 = blockIdx.y * BN;

    extern __shared__ char smem[];
    __shared__ int s_tok[BM];
    uint32_t sb = smem_u32(smem);
    int tid = threadIdx.x;
    int lane = tid & 31;
    int wid = tid >> 5;
    int wm = wid & 3;        // 4 M groups (32 rows)
    int wn = wid >> 2;       // 4 N groups (64 cols)

    for (int m = tid; m < BM; m += 512) s_tok[m] = g_order[row0 + m];

    float acc[2][8][4];
#pragma unroll
    for (int a = 0; a < 2; a++)
#pragma unroll
        for (int b = 0; b < 8; b++)
#pragma unroll
            for (int c = 0; c < 4; c++) acc[a][b][c] = 0.f;

#pragma unroll
    for (int p = 0; p < PIPE - 1; p++) issue_stage(tid, sb, p, row0, e, col0, p * BK);

    // A ldsm (non-trans), R3-proven addressing
    int a_row = wm * 32 + (lane & 15);
    int a_cbit = (lane >> 4) & 1;
    // B ldsm.trans: lane -> k-row (lane&15), n-chunk-half (lane>>4)
    int b_krow = lane & 15;
    int b_chalf = lane >> 4;           // 0/1 -> +0 / +8 cols

    for (int s = 0; s < NKSTAGE; s++) {
        cp_wait<PIPE - 2>();
        __syncthreads();
        if (s + PIPE - 1 < NKSTAGE)
            issue_stage(tid, sb, s + PIPE - 1, row0, e, col0, (s + PIPE - 1) * BK);
        else
            cp_commit();   // keep wait_group accounting aligned

        uint32_t base = sb + (s % PIPE) * STAGE_BYTES;
        uint32_t bbase = base + B_HI;

#pragma unroll
        for (int ks = 0; ks < 2; ks++) {
            uint32_t a[2][4];
#pragma unroll
            for (int mf = 0; mf < 2; mf++)
                ldsm4(a[mf], base + A_OFF + swzA(a_row + mf * 16, ks * 2 + a_cbit));

            int krow = ks * 16 + b_krow;
#pragma unroll
            for (int t = 0; t < 4; t++) {
                // 16x16 region: k rows [ks*16,+16), cols wn*64 + t*16
                int cchunk = wn * 8 + t * 2 + b_chalf;
                uint32_t addr = bbase + swzB(krow, cchunk);
                uint32_t bh[4], bl[4];
                ldsm4t(bh, addr);
                ldsm4t(bl, addr + (B_LO - B_HI));
                // r0,r1 = cols +0..7 (k lo/hi); r2,r3 = cols +8..15
#pragma unroll
                for (int mf = 0; mf < 2; mf++) {
                    MMA(acc[mf][t * 2],     a[mf], bh[0], bh[1]);
                    MMA(acc[mf][t * 2 + 1], a[mf], bh[2], bh[3]);
                }
#pragma unroll
                for (int mf = 0; mf < 2; mf++) {
                    MMA(acc[mf][t * 2],     a[mf], bl[0], bl[1]);
                    MMA(acc[mf][t * 2 + 1], a[mf], bl[2], bl[3]);
                }
            }
        }
    }
    __syncthreads();

    // epilogue: add bias, scatter rows to original token positions
    const float* bias = eb + (size_t)e * D_FF + col0 + wn * 64;
#pragma unroll
    for (int mf = 0; mf < 2; mf++) {
        int r_lo = wm * 32 + mf * 16 + (lane >> 2);
        int t_lo = s_tok[r_lo];
        int t_hi = s_tok[r_lo + 8];
#pragma unroll
        for (int nf = 0; nf < 8; nf++) {
            int cb = nf * 8 + (lane & 3) * 2;
            float b0 = bias[cb], b1 = bias[cb + 1];
            if (t_lo >= 0) {
                float2 v = {acc[mf][nf][0] + b0, acc[mf][nf][1] + b1};
                *(float2*)(out + (size_t)t_lo * D_FF + col0 + wn * 64 + cb) = v;
            }
            if (t_hi >= 0) {
                float2 v = {acc[mf][nf][2] + b0, acc[mf][nf][3] + b1};
                *(float2*)(out + (size_t)t_hi * D_FF + col0 + wn * 64 + cb) = v;
            }
        }
    }
}

extern "C" void kernel_launch(void* const* d_in, const int* in_sizes, int n_in,
                              void* d_out, int out_size) {
    const float* x  = (const float*)d_in[0];
    const float* gw = (const float*)d_in[1];
    const float* gb = (const float*)d_in[2];
    const float* ew = (const float*)d_in[3];
    const float* eb = (const float*)d_in[4];
    float* out = (float*)d_out;

    cudaFuncSetAttribute(k_gemm, cudaFuncAttributeMaxDynamicSharedMemorySize, SMEM_TOTAL);

    k_init<<<(PAD_ROWS + 255) / 256, 256>>>();
    k_gate<<<N_TOKENS / 8, 256>>>(x, gw, gb);
    k_scan<<<1, 1>>>();
    k_scatter<<<N_TOKENS / 256, 256>>>();
    k_half_x<<<PAD_ROWS, 256>>>(x);
    k_wsplit<<<(int)(((size_t)N_EXPERTS * D_MODEL * D_FF) / (256 * 4)), 256>>>(ew);
    {
        dim3 g(MAX_TILES, D_FF / BN);
        k_gemm<<<g, 512, SMEM_TOTAL>>>(eb, out);
    }
}

// round 8
// speedup vs baseline: 5.4111x; 1.3826x over previous
#include <cuda_runtime.h>
#include <cuda_fp16.h>
#include <cstdint>

#define N_TOKENS 8192
#define D_MODEL  1024
#define D_FF     4096
#define N_EXPERTS 8

#define BM 128
#define BN 256
#define BK 32
#define NKSTAGE (D_MODEL / BK)        // 32
#define PIPE 6
#define MAX_TILES 72
#define PAD_ROWS (N_TOKENS + N_EXPERTS * BM)   // 9216

// ---------------- scratch ----------------
__device__ int g_top1[N_TOKENS];
__device__ int g_counts[N_EXPERTS];
__device__ int g_cursor[N_EXPERTS];
__device__ int g_offsets[N_EXPERTS];
__device__ int g_order[PAD_ROWS];              // -1 = pad row
__device__ int g_tile_expert[MAX_TILES + 8];
__device__ int g_tile_row[MAX_TILES + 8];
__device__ int g_ntiles;

__device__ __half g_xh[(size_t)PAD_ROWS * D_MODEL];            // grouped+padded, fp16
__device__ __half g_wh[(size_t)N_EXPERTS * D_MODEL * D_FF];    // W fp16, layout [e][d][f]

// ---------------- helpers ----------------
__device__ __forceinline__ uint32_t smem_u32(const void* p) {
    uint32_t a;
    asm("{ .reg .u64 t; cvta.to.shared.u64 t, %1; cvt.u32.u64 %0, t; }" : "=r"(a) : "l"(p));
    return a;
}
__device__ __forceinline__ void cp16(uint32_t dst, const void* src) {
    asm volatile("cp.async.cg.shared.global [%0], [%1], 16;\n" :: "r"(dst), "l"(src));
}
__device__ __forceinline__ void cp_commit() { asm volatile("cp.async.commit_group;\n" ::: "memory"); }
template <int N> __device__ __forceinline__ void cp_wait() {
    asm volatile("cp.async.wait_group %0;\n" :: "n"(N) : "memory");
}
__device__ __forceinline__ void ldsm4(uint32_t r[4], uint32_t addr) {
    asm volatile("ldmatrix.sync.aligned.m8n8.x4.shared.b16 {%0,%1,%2,%3}, [%4];"
                 : "=r"(r[0]), "=r"(r[1]), "=r"(r[2]), "=r"(r[3]) : "r"(addr));
}
__device__ __forceinline__ void ldsm4t(uint32_t r[4], uint32_t addr) {
    asm volatile("ldmatrix.sync.aligned.m8n8.x4.trans.shared.b16 {%0,%1,%2,%3}, [%4];"
                 : "=r"(r[0]), "=r"(r[1]), "=r"(r[2]), "=r"(r[3]) : "r"(addr));
}
// fp16 MMA, fp32 accumulate
#define MMA(d, a, b0, b1)                                                          \
    asm volatile("mma.sync.aligned.m16n8k16.row.col.f32.f16.f16.f32 "              \
                 "{%0,%1,%2,%3},{%4,%5,%6,%7},{%8,%9},{%0,%1,%2,%3};"              \
                 : "+f"((d)[0]), "+f"((d)[1]), "+f"((d)[2]), "+f"((d)[3])          \
                 : "r"((a)[0]), "r"((a)[1]), "r"((a)[2]), "r"((a)[3]),             \
                   "r"(b0), "r"(b1))

// A tile: 128 rows x 64B (32 fp16), 4x16B chunks, chunk ^= (row>>1)&3  (proven)
__device__ __forceinline__ uint32_t swzA(int row, int c) {
    return (uint32_t)(row * 64 + ((c ^ ((row >> 1) & 3)) << 4));
}
// B tile: 32 k-rows x 512B (256 fp16), 32x16B chunks, chunk ^= row&7   (proven)
__device__ __forceinline__ uint32_t swzB(int row, int c) {
    return (uint32_t)(row * 512 + ((c ^ (row & 7)) << 4));
}

#define A_OFF 0
#define B_OFF 8192
#define STAGE_BYTES 24576
#define SMEM_TOTAL (PIPE * STAGE_BYTES)   // 147456

// ---------------- gate path ----------------
__global__ void k_init() {
    int i = blockIdx.x * blockDim.x + threadIdx.x;
    if (i < N_EXPERTS) { g_counts[i] = 0; g_cursor[i] = 0; }
    if (i < PAD_ROWS) g_order[i] = -1;
}

__global__ void k_gate(const float* __restrict__ x, const float* __restrict__ gw,
                       const float* __restrict__ gb) {
    int warp = (blockIdx.x * blockDim.x + threadIdx.x) >> 5;
    int lane = threadIdx.x & 31;
    if (warp >= N_TOKENS) return;
    const float* xr = x + (size_t)warp * D_MODEL;
    float acc[N_EXPERTS];
#pragma unroll
    for (int e = 0; e < N_EXPERTS; e++) acc[e] = 0.f;
#pragma unroll 4
    for (int i = 0; i < D_MODEL / 32; i++) {
        int d = i * 32 + lane;
        float xv = xr[d];
        const float* g = gw + d * N_EXPERTS;
#pragma unroll
        for (int e = 0; e < N_EXPERTS; e++) acc[e] += xv * g[e];
    }
#pragma unroll
    for (int e = 0; e < N_EXPERTS; e++)
#pragma unroll
        for (int off = 16; off; off >>= 1)
            acc[e] += __shfl_xor_sync(0xffffffffu, acc[e], off);
    if (lane == 0) {
        int best = 0;
        float bv = acc[0] + gb[0];
#pragma unroll
        for (int e = 1; e < N_EXPERTS; e++) {
            float v = acc[e] + gb[e];
            if (v > bv) { bv = v; best = e; }   // first max wins == jnp.argmax
        }
        g_top1[warp] = best;
        atomicAdd(&g_counts[best], 1);
    }
}

__global__ void k_scan() {
    int base = 0, nt = 0;
    for (int e = 0; e < N_EXPERTS; e++) {
        g_offsets[e] = base;
        int c = g_counts[e];
        int t = (c + BM - 1) / BM;
        for (int r = 0; r < t; r++) {
            g_tile_expert[nt] = e;
            g_tile_row[nt] = base + r * BM;
            nt++;
        }
        base += t * BM;
    }
    g_ntiles = nt;
}

__global__ void k_scatter() {
    int n = blockIdx.x * blockDim.x + threadIdx.x;
    if (n >= N_TOKENS) return;
    int e = g_top1[n];
    int pos = g_offsets[e] + atomicAdd(&g_cursor[e], 1);
    g_order[pos] = n;
}

// ---------------- conversions ----------------
// gather token rows into grouped/padded order, fp32 -> fp16
__global__ void k_half_x(const float* __restrict__ x) {
    int pos = blockIdx.x;
    int tok = g_order[pos];
    int c0 = threadIdx.x * 4;
    __half h[4];
    if (tok >= 0) {
        float4 v = *(const float4*)(x + (size_t)tok * D_MODEL + c0);
        h[0] = __float2half(v.x); h[1] = __float2half(v.y);
        h[2] = __float2half(v.z); h[3] = __float2half(v.w);
    } else {
        h[0] = h[1] = h[2] = h[3] = __float2half(0.f);
    }
    *(uint2*)(g_xh + (size_t)pos * D_MODEL + c0) = *(uint2*)h;
}

// elementwise W fp32 -> fp16, same [e][d][f] layout (no transpose)
__global__ void k_whalf(const float* __restrict__ ew) {
    size_t i = ((size_t)blockIdx.x * blockDim.x + threadIdx.x) * 4;
    float4 v = *(const float4*)(ew + i);
    __half h[4];
    h[0] = __float2half(v.x); h[1] = __float2half(v.y);
    h[2] = __float2half(v.z); h[3] = __float2half(v.w);
    *(uint2*)(g_wh + i) = *(uint2*)h;
}

// ---------------- single-term fp16 grouped GEMM ----------------
__device__ __forceinline__ void issue_stage(int tid, uint32_t sb, int stage,
                                            int row0, int e, int col0, int k0) {
    uint32_t base = sb + (stage % PIPE) * STAGE_BYTES;
    // A: 128 rows x 4 chunks = 512 cp16 (1 per thread)
    {
        int row = tid >> 2, c = tid & 3;
        const __half* src = g_xh + (size_t)(row0 + row) * D_MODEL + k0 + c * 8;
        cp16(base + A_OFF + swzA(row, c), src);
    }
    // B: 32 k-rows x 32 chunks = 1024 cp16 (2 per thread)
#pragma unroll
    for (int i = 0; i < 2; i++) {
        int idx = tid + i * 512;
        int row = idx >> 5, c = idx & 31;
        const __half* src = g_wh + ((size_t)e * D_MODEL + k0 + row) * D_FF + col0 + c * 8;
        cp16(base + B_OFF + swzB(row, c), src);
    }
    cp_commit();
}

__global__ void __launch_bounds__(512, 1)
k_gemm(const float* __restrict__ eb, float* __restrict__ out) {
    int tile = blockIdx.x;
    if (tile >= g_ntiles) return;
    int e = g_tile_expert[tile];
    int row0 = g_tile_row[tile];
    int col0 = blockIdx.y * BN;

    extern __shared__ char smem[];
    __shared__ int s_tok[BM];
    uint32_t sb = smem_u32(smem);
    int tid = threadIdx.x;
    int lane = tid & 31;
    int wid = tid >> 5;
    int wm = wid & 3;        // 4 M groups (32 rows)
    int wn = wid >> 2;       // 4 N groups (64 cols)

    for (int m = tid; m < BM; m += 512) s_tok[m] = g_order[row0 + m];

    float acc[2][8][4];
#pragma unroll
    for (int a = 0; a < 2; a++)
#pragma unroll
        for (int b = 0; b < 8; b++)
#pragma unroll
            for (int c = 0; c < 4; c++) acc[a][b][c] = 0.f;

#pragma unroll
    for (int p = 0; p < PIPE - 1; p++) issue_stage(tid, sb, p, row0, e, col0, p * BK);

    // A ldsm (non-trans)
    int a_row = wm * 32 + (lane & 15);
    int a_cbit = (lane >> 4) & 1;
    // B ldsm.trans: lane -> k-row (lane&15), n-chunk-half (lane>>4)
    int b_krow = lane & 15;
    int b_chalf = lane >> 4;

    for (int s = 0; s < NKSTAGE; s++) {
        cp_wait<PIPE - 2>();
        __syncthreads();
        if (s + PIPE - 1 < NKSTAGE)
            issue_stage(tid, sb, s + PIPE - 1, row0, e, col0, (s + PIPE - 1) * BK);
        else
            cp_commit();   // keep wait_group accounting aligned

        uint32_t base = sb + (s % PIPE) * STAGE_BYTES;
        uint32_t bbase = base + B_OFF;

#pragma unroll
        for (int ks = 0; ks < 2; ks++) {
            uint32_t a[2][4];
#pragma unroll
            for (int mf = 0; mf < 2; mf++)
                ldsm4(a[mf], base + A_OFF + swzA(a_row + mf * 16, ks * 2 + a_cbit));

            int krow = ks * 16 + b_krow;
#pragma unroll
            for (int t = 0; t < 4; t++) {
                // 16x16 region: k rows [ks*16,+16), cols wn*64 + t*16
                int cchunk = wn * 8 + t * 2 + b_chalf;
                uint32_t bh[4];
                ldsm4t(bh, bbase + swzB(krow, cchunk));
                // r0,r1 = cols +0..7 (k lo/hi); r2,r3 = cols +8..15
#pragma unroll
                for (int mf = 0; mf < 2; mf++) {
                    MMA(acc[mf][t * 2],     a[mf], bh[0], bh[1]);
                    MMA(acc[mf][t * 2 + 1], a[mf], bh[2], bh[3]);
                }
            }
        }
    }
    __syncthreads();

    // epilogue: add bias, scatter rows to original token positions
    const float* bias = eb + (size_t)e * D_FF + col0 + wn * 64;
#pragma unroll
    for (int mf = 0; mf < 2; mf++) {
        int r_lo = wm * 32 + mf * 16 + (lane >> 2);
        int t_lo = s_tok[r_lo];
        int t_hi = s_tok[r_lo + 8];
#pragma unroll
        for (int nf = 0; nf < 8; nf++) {
            int cb = nf * 8 + (lane & 3) * 2;
            float b0 = bias[cb], b1 = bias[cb + 1];
            if (t_lo >= 0) {
                float2 v = {acc[mf][nf][0] + b0, acc[mf][nf][1] + b1};
                *(float2*)(out + (size_t)t_lo * D_FF + col0 + wn * 64 + cb) = v;
            }
            if (t_hi >= 0) {
                float2 v = {acc[mf][nf][2] + b0, acc[mf][nf][3] + b1};
                *(float2*)(out + (size_t)t_hi * D_FF + col0 + wn * 64 + cb) = v;
            }
        }
    }
}

extern "C" void kernel_launch(void* const* d_in, const int* in_sizes, int n_in,
                              void* d_out, int out_size) {
    const float* x  = (const float*)d_in[0];
    const float* gw = (const float*)d_in[1];
    const float* gb = (const float*)d_in[2];
    const float* ew = (const float*)d_in[3];
    const float* eb = (const float*)d_in[4];
    float* out = (float*)d_out;

    cudaFuncSetAttribute(k_gemm, cudaFuncAttributeMaxDynamicSharedMemorySize, SMEM_TOTAL);

    k_init<<<(PAD_ROWS + 255) / 256, 256>>>();
    k_gate<<<N_TOKENS / 8, 256>>>(x, gw, gb);
    k_scan<<<1, 1>>>();
    k_scatter<<<N_TOKENS / 256, 256>>>();
    k_half_x<<<PAD_ROWS, 256>>>(x);
    k_whalf<<<(int)(((size_t)N_EXPERTS * D_MODEL * D_FF) / (256 * 4)), 256>>>(ew);
    {
        dim3 g(MAX_TILES, D_FF / BN);
        k_gemm<<<g, 512, SMEM_TOTAL>>>(eb, out);
    }
}

// round 9
// speedup vs baseline: 5.9574x; 1.1010x over previous
#include <cuda_runtime.h>
#include <cuda_fp16.h>
#include <cstdint>

#define N_TOKENS 8192
#define D_MODEL  1024
#define D_FF     4096
#define N_EXPERTS 8

#define BM 128
#define BN 256
#define BK 64
#define NKSTAGE (D_MODEL / BK)        // 16
#define PIPE 3
#define MAX_TILES 72
#define PAD_ROWS (N_TOKENS + N_EXPERTS * BM)   // 9216

// ---------------- scratch ----------------
__device__ int g_top1[N_TOKENS];
__device__ int g_counts[N_EXPERTS];
__device__ int g_cursor[N_EXPERTS];
__device__ int g_offsets[N_EXPERTS];
__device__ int g_order[PAD_ROWS];              // -1 = pad row
__device__ int g_tile_expert[MAX_TILES + 8];
__device__ int g_tile_row[MAX_TILES + 8];
__device__ int g_ntiles;

__device__ __half g_xh[(size_t)PAD_ROWS * D_MODEL];            // grouped+padded, fp16
__device__ __half g_wh[(size_t)N_EXPERTS * D_MODEL * D_FF];    // W fp16, layout [e][d][f]

// ---------------- helpers ----------------
__device__ __forceinline__ uint32_t smem_u32(const void* p) {
    uint32_t a;
    asm("{ .reg .u64 t; cvta.to.shared.u64 t, %1; cvt.u32.u64 %0, t; }" : "=r"(a) : "l"(p));
    return a;
}
__device__ __forceinline__ void cp16(uint32_t dst, const void* src) {
    asm volatile("cp.async.cg.shared.global [%0], [%1], 16;\n" :: "r"(dst), "l"(src));
}
__device__ __forceinline__ void cp_commit() { asm volatile("cp.async.commit_group;\n" ::: "memory"); }
template <int N> __device__ __forceinline__ void cp_wait() {
    asm volatile("cp.async.wait_group %0;\n" :: "n"(N) : "memory");
}
__device__ __forceinline__ void ldsm4(uint32_t r[4], uint32_t addr) {
    asm volatile("ldmatrix.sync.aligned.m8n8.x4.shared.b16 {%0,%1,%2,%3}, [%4];"
                 : "=r"(r[0]), "=r"(r[1]), "=r"(r[2]), "=r"(r[3]) : "r"(addr));
}
__device__ __forceinline__ void ldsm4t(uint32_t r[4], uint32_t addr) {
    asm volatile("ldmatrix.sync.aligned.m8n8.x4.trans.shared.b16 {%0,%1,%2,%3}, [%4];"
                 : "=r"(r[0]), "=r"(r[1]), "=r"(r[2]), "=r"(r[3]) : "r"(addr));
}
// fp16 MMA, fp32 accumulate
#define MMA(d, a, b0, b1)                                                          \
    asm volatile("mma.sync.aligned.m16n8k16.row.col.f32.f16.f16.f32 "              \
                 "{%0,%1,%2,%3},{%4,%5,%6,%7},{%8,%9},{%0,%1,%2,%3};"              \
                 : "+f"((d)[0]), "+f"((d)[1]), "+f"((d)[2]), "+f"((d)[3])          \
                 : "r"((a)[0]), "r"((a)[1]), "r"((a)[2]), "r"((a)[3]),             \
                   "r"(b0), "r"(b1))

// A tile: 128 rows x 128B (64 fp16), 8x16B chunks, chunk ^= row&7 (full 8-way)
__device__ __forceinline__ uint32_t swzA(int row, int c) {
    return (uint32_t)(row * 128 + ((c ^ (row & 7)) << 4));
}
// B tile: 64 k-rows x 512B (256 fp16), 32x16B chunks, chunk ^= row&7
__device__ __forceinline__ uint32_t swzB(int row, int c) {
    return (uint32_t)(row * 512 + ((c ^ (row & 7)) << 4));
}

#define A_OFF 0
#define B_OFF 16384
#define STAGE_BYTES 49152          // A 16K + B 32K
#define SMEM_TOTAL (PIPE * STAGE_BYTES)   // 147456

// ---------------- gate path ----------------
__global__ void k_init() {
    int i = blockIdx.x * blockDim.x + threadIdx.x;
    if (i < N_EXPERTS) { g_counts[i] = 0; g_cursor[i] = 0; }
    if (i < PAD_ROWS) g_order[i] = -1;
}

__global__ void k_gate(const float* __restrict__ x, const float* __restrict__ gw,
                       const float* __restrict__ gb) {
    int warp = (blockIdx.x * blockDim.x + threadIdx.x) >> 5;
    int lane = threadIdx.x & 31;
    if (warp >= N_TOKENS) return;
    const float* xr = x + (size_t)warp * D_MODEL;
    float acc[N_EXPERTS];
#pragma unroll
    for (int e = 0; e < N_EXPERTS; e++) acc[e] = 0.f;
#pragma unroll 4
    for (int i = 0; i < D_MODEL / 32; i++) {
        int d = i * 32 + lane;
        float xv = xr[d];
        const float* g = gw + d * N_EXPERTS;
#pragma unroll
        for (int e = 0; e < N_EXPERTS; e++) acc[e] += xv * g[e];
    }
#pragma unroll
    for (int e = 0; e < N_EXPERTS; e++)
#pragma unroll
        for (int off = 16; off; off >>= 1)
            acc[e] += __shfl_xor_sync(0xffffffffu, acc[e], off);
    if (lane == 0) {
        int best = 0;
        float bv = acc[0] + gb[0];
#pragma unroll
        for (int e = 1; e < N_EXPERTS; e++) {
            float v = acc[e] + gb[e];
            if (v > bv) { bv = v; best = e; }   // first max wins == jnp.argmax
        }
        g_top1[warp] = best;
        atomicAdd(&g_counts[best], 1);
    }
}

__global__ void k_scan() {
    int base = 0, nt = 0;
    for (int e = 0; e < N_EXPERTS; e++) {
        g_offsets[e] = base;
        int c = g_counts[e];
        int t = (c + BM - 1) / BM;
        for (int r = 0; r < t; r++) {
            g_tile_expert[nt] = e;
            g_tile_row[nt] = base + r * BM;
            nt++;
        }
        base += t * BM;
    }
    g_ntiles = nt;
}

__global__ void k_scatter() {
    int n = blockIdx.x * blockDim.x + threadIdx.x;
    if (n >= N_TOKENS) return;
    int e = g_top1[n];
    int pos = g_offsets[e] + atomicAdd(&g_cursor[e], 1);
    g_order[pos] = n;
}

// ---------------- conversions ----------------
// gather token rows into grouped/padded order, fp32 -> fp16
__global__ void k_half_x(const float* __restrict__ x) {
    int pos = blockIdx.x;
    int tok = g_order[pos];
    int c0 = threadIdx.x * 4;
    __half h[4];
    if (tok >= 0) {
        float4 v = *(const float4*)(x + (size_t)tok * D_MODEL + c0);
        h[0] = __float2half(v.x); h[1] = __float2half(v.y);
        h[2] = __float2half(v.z); h[3] = __float2half(v.w);
    } else {
        h[0] = h[1] = h[2] = h[3] = __float2half(0.f);
    }
    *(uint2*)(g_xh + (size_t)pos * D_MODEL + c0) = *(uint2*)h;
}

// elementwise W fp32 -> fp16, 8 elems/thread (32B read, 16B write)
__global__ void k_whalf(const float* __restrict__ ew) {
    size_t i = ((size_t)blockIdx.x * blockDim.x + threadIdx.x) * 8;
    float4 v0 = *(const float4*)(ew + i);
    float4 v1 = *(const float4*)(ew + i + 4);
    __half h[8];
    h[0] = __float2half(v0.x); h[1] = __float2half(v0.y);
    h[2] = __float2half(v0.z); h[3] = __float2half(v0.w);
    h[4] = __float2half(v1.x); h[5] = __float2half(v1.y);
    h[6] = __float2half(v1.z); h[7] = __float2half(v1.w);
    *(uint4*)(g_wh + i) = *(uint4*)h;
}

// ---------------- single-term fp16 grouped GEMM ----------------
__device__ __forceinline__ void issue_stage(int tid, uint32_t sb, int stage,
                                            int row0, int e, int col0, int k0) {
    uint32_t base = sb + (stage % PIPE) * STAGE_BYTES;
    // A: 128 rows x 8 chunks = 1024 cp16 (2 per thread)
#pragma unroll
    for (int i = 0; i < 2; i++) {
        int idx = tid + i * 512;
        int row = idx >> 3, c = idx & 7;
        const __half* src = g_xh + (size_t)(row0 + row) * D_MODEL + k0 + c * 8;
        cp16(base + A_OFF + swzA(row, c), src);
    }
    // B: 64 k-rows x 32 chunks = 2048 cp16 (4 per thread)
#pragma unroll
    for (int i = 0; i < 4; i++) {
        int idx = tid + i * 512;
        int row = idx >> 5, c = idx & 31;
        const __half* src = g_wh + ((size_t)e * D_MODEL + k0 + row) * D_FF + col0 + c * 8;
        cp16(base + B_OFF + swzB(row, c), src);
    }
    cp_commit();
}

__global__ void __launch_bounds__(512, 1)
k_gemm(const float* __restrict__ eb, float* __restrict__ out) {
    int tile = blockIdx.x;
    if (tile >= g_ntiles) return;
    int e = g_tile_expert[tile];
    int row0 = g_tile_row[tile];
    int col0 = blockIdx.y * BN;

    extern __shared__ char smem[];
    __shared__ int s_tok[BM];
    uint32_t sb = smem_u32(smem);
    int tid = threadIdx.x;
    int lane = tid & 31;
    int wid = tid >> 5;
    int wm = wid & 3;        // 4 M groups (32 rows)
    int wn = wid >> 2;       // 4 N groups (64 cols)

    for (int m = tid; m < BM; m += 512) s_tok[m] = g_order[row0 + m];

    float acc[2][8][4];
#pragma unroll
    for (int a = 0; a < 2; a++)
#pragma unroll
        for (int b = 0; b < 8; b++)
#pragma unroll
            for (int c = 0; c < 4; c++) acc[a][b][c] = 0.f;

#pragma unroll
    for (int p = 0; p < PIPE - 1; p++) issue_stage(tid, sb, p, row0, e, col0, p * BK);

    // A ldsm (non-trans): lanes 0-15 -> rows, chunk = ks*2 + (lane>>4)
    int a_row = wm * 32 + (lane & 15);
    int a_cbit = (lane >> 4) & 1;
    // B ldsm.trans: lane -> k-row (lane&15), n-chunk-half (lane>>4)
    int b_krow = lane & 15;
    int b_chalf = lane >> 4;

    for (int s = 0; s < NKSTAGE; s++) {
        cp_wait<PIPE - 2>();
        __syncthreads();
        if (s + PIPE - 1 < NKSTAGE)
            issue_stage(tid, sb, s + PIPE - 1, row0, e, col0, (s + PIPE - 1) * BK);
        else
            cp_commit();   // keep wait_group accounting aligned

        uint32_t base = sb + (s % PIPE) * STAGE_BYTES;
        uint32_t bbase = base + B_OFF;

#pragma unroll
        for (int ks = 0; ks < 4; ks++) {        // 4 K-substeps of 16
            uint32_t a[2][4];
#pragma unroll
            for (int mf = 0; mf < 2; mf++)
                ldsm4(a[mf], base + A_OFF + swzA(a_row + mf * 16, ks * 2 + a_cbit));

            int krow = ks * 16 + b_krow;
#pragma unroll
            for (int t = 0; t < 4; t++) {
                // 16x16 region: k rows [ks*16,+16), cols wn*64 + t*16
                int cchunk = wn * 8 + t * 2 + b_chalf;
                uint32_t bh[4];
                ldsm4t(bh, bbase + swzB(krow, cchunk));
                // r0,r1 = cols +0..7 (k lo/hi); r2,r3 = cols +8..15
#pragma unroll
                for (int mf = 0; mf < 2; mf++) {
                    MMA(acc[mf][t * 2],     a[mf], bh[0], bh[1]);
                    MMA(acc[mf][t * 2 + 1], a[mf], bh[2], bh[3]);
                }
            }
        }
    }
    __syncthreads();

    // epilogue: add bias, scatter rows to original token positions
    const float* bias = eb + (size_t)e * D_FF + col0 + wn * 64;
#pragma unroll
    for (int mf = 0; mf < 2; mf++) {
        int r_lo = wm * 32 + mf * 16 + (lane >> 2);
        int t_lo = s_tok[r_lo];
        int t_hi = s_tok[r_lo + 8];
#pragma unroll
        for (int nf = 0; nf < 8; nf++) {
            int cb = nf * 8 + (lane & 3) * 2;
            float b0 = bias[cb], b1 = bias[cb + 1];
            if (t_lo >= 0) {
                float2 v = {acc[mf][nf][0] + b0, acc[mf][nf][1] + b1};
                *(float2*)(out + (size_t)t_lo * D_FF + col0 + wn * 64 + cb) = v;
            }
            if (t_hi >= 0) {
                float2 v = {acc[mf][nf][2] + b0, acc[mf][nf][3] + b1};
                *(float2*)(out + (size_t)t_hi * D_FF + col0 + wn * 64 + cb) = v;
            }
        }
    }
}

extern "C" void kernel_launch(void* const* d_in, const int* in_sizes, int n_in,
                              void* d_out, int out_size) {
    const float* x  = (const float*)d_in[0];
    const float* gw = (const float*)d_in[1];
    const float* gb = (const float*)d_in[2];
    const float* ew = (const float*)d_in[3];
    const float* eb = (const float*)d_in[4];
    float* out = (float*)d_out;

    cudaFuncSetAttribute(k_gemm, cudaFuncAttributeMaxDynamicSharedMemorySize, SMEM_TOTAL);

    k_init<<<(PAD_ROWS + 255) / 256, 256>>>();
    k_gate<<<N_TOKENS / 8, 256>>>(x, gw, gb);
    k_scan<<<1, 1>>>();
    k_scatter<<<N_TOKENS / 256, 256>>>();
    k_half_x<<<PAD_ROWS, 256>>>(x);
    k_whalf<<<(int)(((size_t)N_EXPERTS * D_MODEL * D_FF) / (256 * 8)), 256>>>(ew);
    {
        dim3 g(MAX_TILES, D_FF / BN);
        k_gemm<<<g, 512, SMEM_TOTAL>>>(eb, out);
    }
}

// round 10
// speedup vs baseline: 5.9684x; 1.0018x over previous
#include <cuda_runtime.h>
#include <cuda_fp16.h>
#include <cstdint>

#define N_TOKENS 8192
#define D_MODEL  1024
#define D_FF     4096
#define N_EXPERTS 8

#define BM 128
#define BN 256
#define BK 64
#define NKSTAGE (D_MODEL / BK)        // 16
#define PIPE 3
#define MAX_TILES 72
#define PAD_ROWS (N_TOKENS + N_EXPERTS * BM)   // 9216
#define NTHREADS 256

// ---------------- scratch ----------------
__device__ int g_top1[N_TOKENS];
__device__ int g_counts[N_EXPERTS];
__device__ int g_cursor[N_EXPERTS];
__device__ int g_offsets[N_EXPERTS];
__device__ int g_order[PAD_ROWS];              // -1 = pad row
__device__ int g_tile_expert[MAX_TILES + 8];
__device__ int g_tile_row[MAX_TILES + 8];
__device__ int g_ntiles;

__device__ __half g_xh[(size_t)PAD_ROWS * D_MODEL];            // grouped+padded, fp16
__device__ __half g_wh[(size_t)N_EXPERTS * D_MODEL * D_FF];    // W fp16, layout [e][d][f]

// ---------------- helpers ----------------
__device__ __forceinline__ uint32_t smem_u32(const void* p) {
    uint32_t a;
    asm("{ .reg .u64 t; cvta.to.shared.u64 t, %1; cvt.u32.u64 %0, t; }" : "=r"(a) : "l"(p));
    return a;
}
__device__ __forceinline__ void cp16(uint32_t dst, const void* src) {
    asm volatile("cp.async.cg.shared.global [%0], [%1], 16;\n" :: "r"(dst), "l"(src));
}
__device__ __forceinline__ void cp_commit() { asm volatile("cp.async.commit_group;\n" ::: "memory"); }
template <int N> __device__ __forceinline__ void cp_wait() {
    asm volatile("cp.async.wait_group %0;\n" :: "n"(N) : "memory");
}
__device__ __forceinline__ void ldsm4(uint32_t r[4], uint32_t addr) {
    asm volatile("ldmatrix.sync.aligned.m8n8.x4.shared.b16 {%0,%1,%2,%3}, [%4];"
                 : "=r"(r[0]), "=r"(r[1]), "=r"(r[2]), "=r"(r[3]) : "r"(addr));
}
__device__ __forceinline__ void ldsm4t(uint32_t r[4], uint32_t addr) {
    asm volatile("ldmatrix.sync.aligned.m8n8.x4.trans.shared.b16 {%0,%1,%2,%3}, [%4];"
                 : "=r"(r[0]), "=r"(r[1]), "=r"(r[2]), "=r"(r[3]) : "r"(addr));
}
// fp16 MMA, fp32 accumulate
#define MMA(d, a, b0, b1)                                                          \
    asm volatile("mma.sync.aligned.m16n8k16.row.col.f32.f16.f16.f32 "              \
                 "{%0,%1,%2,%3},{%4,%5,%6,%7},{%8,%9},{%0,%1,%2,%3};"              \
                 : "+f"((d)[0]), "+f"((d)[1]), "+f"((d)[2]), "+f"((d)[3])          \
                 : "r"((a)[0]), "r"((a)[1]), "r"((a)[2]), "r"((a)[3]),             \
                   "r"(b0), "r"(b1))

// A tile: 128 rows x 128B (64 fp16), 8x16B chunks, chunk ^= row&7 (proven)
__device__ __forceinline__ uint32_t swzA(int row, int c) {
    return (uint32_t)(row * 128 + ((c ^ (row & 7)) << 4));
}
// B tile: 64 k-rows x 512B (256 fp16), 32x16B chunks, chunk ^= row&7 (proven)
__device__ __forceinline__ uint32_t swzB(int row, int c) {
    return (uint32_t)(row * 512 + ((c ^ (row & 7)) << 4));
}

#define A_OFF 0
#define B_OFF 16384
#define STAGE_BYTES 49152          // A 16K + B 32K
#define SMEM_TOTAL (PIPE * STAGE_BYTES)   // 147456

// ---------------- gate path ----------------
__global__ void k_init() {
    int i = blockIdx.x * blockDim.x + threadIdx.x;
    if (i < N_EXPERTS) { g_counts[i] = 0; g_cursor[i] = 0; }
    if (i < PAD_ROWS) g_order[i] = -1;
}

__global__ void k_gate(const float* __restrict__ x, const float* __restrict__ gw,
                       const float* __restrict__ gb) {
    int warp = (blockIdx.x * blockDim.x + threadIdx.x) >> 5;
    int lane = threadIdx.x & 31;
    if (warp >= N_TOKENS) return;
    const float* xr = x + (size_t)warp * D_MODEL;
    float acc[N_EXPERTS];
#pragma unroll
    for (int e = 0; e < N_EXPERTS; e++) acc[e] = 0.f;
#pragma unroll 4
    for (int i = 0; i < D_MODEL / 32; i++) {
        int d = i * 32 + lane;
        float xv = xr[d];
        const float* g = gw + d * N_EXPERTS;
#pragma unroll
        for (int e = 0; e < N_EXPERTS; e++) acc[e] += xv * g[e];
    }
#pragma unroll
    for (int e = 0; e < N_EXPERTS; e++)
#pragma unroll
        for (int off = 16; off; off >>= 1)
            acc[e] += __shfl_xor_sync(0xffffffffu, acc[e], off);
    if (lane == 0) {
        int best = 0;
        float bv = acc[0] + gb[0];
#pragma unroll
        for (int e = 1; e < N_EXPERTS; e++) {
            float v = acc[e] + gb[e];
            if (v > bv) { bv = v; best = e; }   // first max wins == jnp.argmax
        }
        g_top1[warp] = best;
        atomicAdd(&g_counts[best], 1);
    }
}

__global__ void k_scan() {
    int base = 0, nt = 0;
    for (int e = 0; e < N_EXPERTS; e++) {
        g_offsets[e] = base;
        int c = g_counts[e];
        int t = (c + BM - 1) / BM;
        for (int r = 0; r < t; r++) {
            g_tile_expert[nt] = e;
            g_tile_row[nt] = base + r * BM;
            nt++;
        }
        base += t * BM;
    }
    g_ntiles = nt;
}

__global__ void k_scatter() {
    int n = blockIdx.x * blockDim.x + threadIdx.x;
    if (n >= N_TOKENS) return;
    int e = g_top1[n];
    int pos = g_offsets[e] + atomicAdd(&g_cursor[e], 1);
    g_order[pos] = n;
}

// ---------------- conversions ----------------
// gather token rows into grouped/padded order, fp32 -> fp16
__global__ void k_half_x(const float* __restrict__ x) {
    int pos = blockIdx.x;
    int tok = g_order[pos];
    int c0 = threadIdx.x * 4;
    __half h[4];
    if (tok >= 0) {
        float4 v = *(const float4*)(x + (size_t)tok * D_MODEL + c0);
        h[0] = __float2half(v.x); h[1] = __float2half(v.y);
        h[2] = __float2half(v.z); h[3] = __float2half(v.w);
    } else {
        h[0] = h[1] = h[2] = h[3] = __float2half(0.f);
    }
    *(uint2*)(g_xh + (size_t)pos * D_MODEL + c0) = *(uint2*)h;
}

// elementwise W fp32 -> fp16, 8 elems/thread (32B read, 16B write)
__global__ void k_whalf(const float* __restrict__ ew) {
    size_t i = ((size_t)blockIdx.x * blockDim.x + threadIdx.x) * 8;
    float4 v0 = *(const float4*)(ew + i);
    float4 v1 = *(const float4*)(ew + i + 4);
    __half h[8];
    h[0] = __float2half(v0.x); h[1] = __float2half(v0.y);
    h[2] = __float2half(v0.z); h[3] = __float2half(v0.w);
    h[4] = __float2half(v1.x); h[5] = __float2half(v1.y);
    h[6] = __float2half(v1.z); h[7] = __float2half(v1.w);
    *(uint4*)(g_wh + i) = *(uint4*)h;
}

// ---------------- single-term fp16 grouped GEMM (8 warps, 64x64 warp tile) ----------------
__device__ __forceinline__ void issue_stage(int tid, uint32_t sb, int stage,
                                            int row0, int e, int col0, int k0) {
    uint32_t base = sb + (stage % PIPE) * STAGE_BYTES;
    // A: 128 rows x 8 chunks = 1024 cp16 (4 per thread)
#pragma unroll
    for (int i = 0; i < 4; i++) {
        int idx = tid + i * NTHREADS;
        int row = idx >> 3, c = idx & 7;
        const __half* src = g_xh + (size_t)(row0 + row) * D_MODEL + k0 + c * 8;
        cp16(base + A_OFF + swzA(row, c), src);
    }
    // B: 64 k-rows x 32 chunks = 2048 cp16 (8 per thread)
#pragma unroll
    for (int i = 0; i < 8; i++) {
        int idx = tid + i * NTHREADS;
        int row = idx >> 5, c = idx & 31;
        const __half* src = g_wh + ((size_t)e * D_MODEL + k0 + row) * D_FF + col0 + c * 8;
        cp16(base + B_OFF + swzB(row, c), src);
    }
    cp_commit();
}

__global__ void __launch_bounds__(NTHREADS, 1)
k_gemm(const float* __restrict__ eb, float* __restrict__ out) {
    int tile = blockIdx.x;
    if (tile >= g_ntiles) return;
    int e = g_tile_expert[tile];
    int row0 = g_tile_row[tile];
    int col0 = blockIdx.y * BN;

    extern __shared__ char smem[];
    __shared__ int s_tok[BM];
    uint32_t sb = smem_u32(smem);
    int tid = threadIdx.x;
    int lane = tid & 31;
    int wid = tid >> 5;      // 8 warps
    int wm = wid & 1;        // 2 M groups (64 rows)
    int wn = wid >> 1;       // 4 N groups (64 cols)

    for (int m = tid; m < BM; m += NTHREADS) s_tok[m] = g_order[row0 + m];

    float acc[4][8][4];      // [m-frag 16][n-frag 8][quad] = 128 regs
#pragma unroll
    for (int a = 0; a < 4; a++)
#pragma unroll
        for (int b = 0; b < 8; b++)
#pragma unroll
            for (int c = 0; c < 4; c++) acc[a][b][c] = 0.f;

#pragma unroll
    for (int p = 0; p < PIPE - 1; p++) issue_stage(tid, sb, p, row0, e, col0, p * BK);

    // A ldsm (non-trans): lanes 0-15 -> rows, chunk = ks*2 + (lane>>4)
    int a_row = wm * 64 + (lane & 15);
    int a_cbit = (lane >> 4) & 1;
    // B ldsm.trans: lane -> k-row (lane&15), n-chunk-half (lane>>4)
    int b_krow = lane & 15;
    int b_chalf = lane >> 4;

    for (int s = 0; s < NKSTAGE; s++) {
        cp_wait<PIPE - 2>();
        __syncthreads();
        if (s + PIPE - 1 < NKSTAGE)
            issue_stage(tid, sb, s + PIPE - 1, row0, e, col0, (s + PIPE - 1) * BK);
        else
            cp_commit();   // keep wait_group accounting aligned

        uint32_t base = sb + (s % PIPE) * STAGE_BYTES;
        uint32_t bbase = base + B_OFF;

#pragma unroll
        for (int ks = 0; ks < 4; ks++) {        // 4 K-substeps of 16
            uint32_t a[4][4];
#pragma unroll
            for (int mf = 0; mf < 4; mf++)
                ldsm4(a[mf], base + A_OFF + swzA(a_row + mf * 16, ks * 2 + a_cbit));

            int krow = ks * 16 + b_krow;
#pragma unroll
            for (int t = 0; t < 4; t++) {
                // 16x16 region: k rows [ks*16,+16), cols wn*64 + t*16
                int cchunk = wn * 8 + t * 2 + b_chalf;
                uint32_t bh[4];
                ldsm4t(bh, bbase + swzB(krow, cchunk));
                // r0,r1 = cols +0..7 (k lo/hi); r2,r3 = cols +8..15
#pragma unroll
                for (int mf = 0; mf < 4; mf++) {
                    MMA(acc[mf][t * 2],     a[mf], bh[0], bh[1]);
                    MMA(acc[mf][t * 2 + 1], a[mf], bh[2], bh[3]);
                }
            }
        }
    }
    __syncthreads();

    // epilogue: add bias, scatter rows to original token positions
    const float* bias = eb + (size_t)e * D_FF + col0 + wn * 64;
#pragma unroll
    for (int mf = 0; mf < 4; mf++) {
        int r_lo = wm * 64 + mf * 16 + (lane >> 2);
        int t_lo = s_tok[r_lo];
        int t_hi = s_tok[r_lo + 8];
#pragma unroll
        for (int nf = 0; nf < 8; nf++) {
            int cb = nf * 8 + (lane & 3) * 2;
            float b0 = bias[cb], b1 = bias[cb + 1];
            if (t_lo >= 0) {
                float2 v = {acc[mf][nf][0] + b0, acc[mf][nf][1] + b1};
                *(float2*)(out + (size_t)t_lo * D_FF + col0 + wn * 64 + cb) = v;
            }
            if (t_hi >= 0) {
                float2 v = {acc[mf][nf][2] + b0, acc[mf][nf][3] + b1};
                *(float2*)(out + (size_t)t_hi * D_FF + col0 + wn * 64 + cb) = v;
            }
        }
    }
}

extern "C" void kernel_launch(void* const* d_in, const int* in_sizes, int n_in,
                              void* d_out, int out_size) {
    const float* x  = (const float*)d_in[0];
    const float* gw = (const float*)d_in[1];
    const float* gb = (const float*)d_in[2];
    const float* ew = (const float*)d_in[3];
    const float* eb = (const float*)d_in[4];
    float* out = (float*)d_out;

    cudaFuncSetAttribute(k_gemm, cudaFuncAttributeMaxDynamicSharedMemorySize, SMEM_TOTAL);

    k_init<<<(PAD_ROWS + 255) / 256, 256>>>();
    k_gate<<<N_TOKENS / 8, 256>>>(x, gw, gb);
    k_scan<<<1, 1>>>();
    k_scatter<<<N_TOKENS / 256, 256>>>();
    k_half_x<<<PAD_ROWS, 256>>>(x);
    k_whalf<<<(int)(((size_t)N_EXPERTS * D_MODEL * D_FF) / (256 * 8)), 256>>>(ew);
    {
        dim3 g(MAX_TILES, D_FF / BN);
        k_gemm<<<g, NTHREADS, SMEM_TOTAL>>>(eb, out);
    }
}

// round 11
// speedup vs baseline: 6.1944x; 1.0379x over previous
#include <cuda_runtime.h>
#include <cuda_fp16.h>
#include <cstdint>

#define N_TOKENS 8192
#define D_MODEL  1024
#define D_FF     4096
#define N_EXPERTS 8

#define BM 128
#define BN 128
#define BK 64
#define NKSTAGE (D_MODEL / BK)        // 16
#define PIPE 3
#define MAX_TILES 72
#define PAD_ROWS (N_TOKENS + N_EXPERTS * BM)   // 9216
#define NTHREADS 256

// ---------------- scratch ----------------
__device__ int g_top1[N_TOKENS];
__device__ int g_counts[N_EXPERTS];
__device__ int g_cursor[N_EXPERTS];
__device__ int g_offsets[N_EXPERTS];
__device__ int g_order[PAD_ROWS];              // -1 = pad row
__device__ int g_tile_expert[MAX_TILES + 8];
__device__ int g_tile_row[MAX_TILES + 8];
__device__ int g_ntiles;

__device__ __half g_xh[(size_t)PAD_ROWS * D_MODEL];            // grouped+padded, fp16
__device__ __half g_wh[(size_t)N_EXPERTS * D_MODEL * D_FF];    // W fp16, layout [e][d][f]

// ---------------- helpers ----------------
__device__ __forceinline__ uint32_t smem_u32(const void* p) {
    uint32_t a;
    asm("{ .reg .u64 t; cvta.to.shared.u64 t, %1; cvt.u32.u64 %0, t; }" : "=r"(a) : "l"(p));
    return a;
}
__device__ __forceinline__ void cp16(uint32_t dst, const void* src) {
    asm volatile("cp.async.cg.shared.global [%0], [%1], 16;\n" :: "r"(dst), "l"(src));
}
__device__ __forceinline__ void cp_commit() { asm volatile("cp.async.commit_group;\n" ::: "memory"); }
template <int N> __device__ __forceinline__ void cp_wait() {
    asm volatile("cp.async.wait_group %0;\n" :: "n"(N) : "memory");
}
__device__ __forceinline__ void ldsm4(uint32_t r[4], uint32_t addr) {
    asm volatile("ldmatrix.sync.aligned.m8n8.x4.shared.b16 {%0,%1,%2,%3}, [%4];"
                 : "=r"(r[0]), "=r"(r[1]), "=r"(r[2]), "=r"(r[3]) : "r"(addr));
}
__device__ __forceinline__ void ldsm4t(uint32_t r[4], uint32_t addr) {
    asm volatile("ldmatrix.sync.aligned.m8n8.x4.trans.shared.b16 {%0,%1,%2,%3}, [%4];"
                 : "=r"(r[0]), "=r"(r[1]), "=r"(r[2]), "=r"(r[3]) : "r"(addr));
}
// fp16 MMA, fp32 accumulate
#define MMA(d, a, b0, b1)                                                          \
    asm volatile("mma.sync.aligned.m16n8k16.row.col.f32.f16.f16.f32 "              \
                 "{%0,%1,%2,%3},{%4,%5,%6,%7},{%8,%9},{%0,%1,%2,%3};"              \
                 : "+f"((d)[0]), "+f"((d)[1]), "+f"((d)[2]), "+f"((d)[3])          \
                 : "r"((a)[0]), "r"((a)[1]), "r"((a)[2]), "r"((a)[3]),             \
                   "r"(b0), "r"(b1))

// A tile: 128 rows x 128B (64 fp16), 8x16B chunks, chunk ^= row&7 (proven)
__device__ __forceinline__ uint32_t swzA(int row, int c) {
    return (uint32_t)(row * 128 + ((c ^ (row & 7)) << 4));
}
// B tile: 64 k-rows x 256B (128 fp16), 16x16B chunks, chunk ^= row&7
__device__ __forceinline__ uint32_t swzB(int row, int c) {
    return (uint32_t)(row * 256 + ((c ^ (row & 7)) << 4));
}

#define A_OFF 0
#define B_OFF 16384
#define STAGE_BYTES 32768          // A 16K + B 16K
#define SMEM_TOTAL (PIPE * STAGE_BYTES)   // 98304 -> 2 CTAs/SM

// ---------------- gate path ----------------
__global__ void k_init() {
    int i = blockIdx.x * blockDim.x + threadIdx.x;
    if (i < N_EXPERTS) { g_counts[i] = 0; g_cursor[i] = 0; }
    if (i < PAD_ROWS) g_order[i] = -1;
}

__global__ void k_gate(const float* __restrict__ x, const float* __restrict__ gw,
                       const float* __restrict__ gb) {
    int warp = (blockIdx.x * blockDim.x + threadIdx.x) >> 5;
    int lane = threadIdx.x & 31;
    if (warp >= N_TOKENS) return;
    const float* xr = x + (size_t)warp * D_MODEL;
    float acc[N_EXPERTS];
#pragma unroll
    for (int e = 0; e < N_EXPERTS; e++) acc[e] = 0.f;
#pragma unroll 4
    for (int i = 0; i < D_MODEL / 32; i++) {
        int d = i * 32 + lane;
        float xv = xr[d];
        const float* g = gw + d * N_EXPERTS;
#pragma unroll
        for (int e = 0; e < N_EXPERTS; e++) acc[e] += xv * g[e];
    }
#pragma unroll
    for (int e = 0; e < N_EXPERTS; e++)
#pragma unroll
        for (int off = 16; off; off >>= 1)
            acc[e] += __shfl_xor_sync(0xffffffffu, acc[e], off);
    if (lane == 0) {
        int best = 0;
        float bv = acc[0] + gb[0];
#pragma unroll
        for (int e = 1; e < N_EXPERTS; e++) {
            float v = acc[e] + gb[e];
            if (v > bv) { bv = v; best = e; }   // first max wins == jnp.argmax
        }
        g_top1[warp] = best;
        atomicAdd(&g_counts[best], 1);
    }
}

__global__ void k_scan() {
    int base = 0, nt = 0;
    for (int e = 0; e < N_EXPERTS; e++) {
        g_offsets[e] = base;
        int c = g_counts[e];
        int t = (c + BM - 1) / BM;
        for (int r = 0; r < t; r++) {
            g_tile_expert[nt] = e;
            g_tile_row[nt] = base + r * BM;
            nt++;
        }
        base += t * BM;
    }
    g_ntiles = nt;
}

__global__ void k_scatter() {
    int n = blockIdx.x * blockDim.x + threadIdx.x;
    if (n >= N_TOKENS) return;
    int e = g_top1[n];
    int pos = g_offsets[e] + atomicAdd(&g_cursor[e], 1);
    g_order[pos] = n;
}

// ---------------- conversions ----------------
// gather token rows into grouped/padded order, fp32 -> fp16
__global__ void k_half_x(const float* __restrict__ x) {
    int pos = blockIdx.x;
    int tok = g_order[pos];
    int c0 = threadIdx.x * 4;
    __half h[4];
    if (tok >= 0) {
        float4 v = *(const float4*)(x + (size_t)tok * D_MODEL + c0);
        h[0] = __float2half(v.x); h[1] = __float2half(v.y);
        h[2] = __float2half(v.z); h[3] = __float2half(v.w);
    } else {
        h[0] = h[1] = h[2] = h[3] = __float2half(0.f);
    }
    *(uint2*)(g_xh + (size_t)pos * D_MODEL + c0) = *(uint2*)h;
}

// elementwise W fp32 -> fp16, 8 elems/thread (32B read, 16B write)
__global__ void k_whalf(const float* __restrict__ ew) {
    size_t i = ((size_t)blockIdx.x * blockDim.x + threadIdx.x) * 8;
    float4 v0 = *(const float4*)(ew + i);
    float4 v1 = *(const float4*)(ew + i + 4);
    __half h[8];
    h[0] = __float2half(v0.x); h[1] = __float2half(v0.y);
    h[2] = __float2half(v0.z); h[3] = __float2half(v0.w);
    h[4] = __float2half(v1.x); h[5] = __float2half(v1.y);
    h[6] = __float2half(v1.z); h[7] = __float2half(v1.w);
    *(uint4*)(g_wh + i) = *(uint4*)h;
}

// ---------------- single-term fp16 grouped GEMM (2 CTAs/SM, warp tile 64x32) ----------------
__device__ __forceinline__ void issue_stage(int tid, uint32_t sb, int stage,
                                            int row0, int e, int col0, int k0) {
    uint32_t base = sb + (stage % PIPE) * STAGE_BYTES;
    // A: 128 rows x 8 chunks = 1024 cp16 (4 per thread)
#pragma unroll
    for (int i = 0; i < 4; i++) {
        int idx = tid + i * NTHREADS;
        int row = idx >> 3, c = idx & 7;
        const __half* src = g_xh + (size_t)(row0 + row) * D_MODEL + k0 + c * 8;
        cp16(base + A_OFF + swzA(row, c), src);
    }
    // B: 64 k-rows x 16 chunks = 1024 cp16 (4 per thread)
#pragma unroll
    for (int i = 0; i < 4; i++) {
        int idx = tid + i * NTHREADS;
        int row = idx >> 4, c = idx & 15;
        const __half* src = g_wh + ((size_t)e * D_MODEL + k0 + row) * D_FF + col0 + c * 8;
        cp16(base + B_OFF + swzB(row, c), src);
    }
    cp_commit();
}

__global__ void __launch_bounds__(NTHREADS, 2)
k_gemm(const float* __restrict__ eb, float* __restrict__ out) {
    int tile = blockIdx.x;
    if (tile >= g_ntiles) return;
    int e = g_tile_expert[tile];
    int row0 = g_tile_row[tile];
    int col0 = blockIdx.y * BN;

    extern __shared__ char smem[];
    __shared__ int s_tok[BM];
    uint32_t sb = smem_u32(smem);
    int tid = threadIdx.x;
    int lane = tid & 31;
    int wid = tid >> 5;      // 8 warps
    int wm = wid & 1;        // 2 M groups (64 rows)
    int wn = wid >> 1;       // 4 N groups (32 cols)

    for (int m = tid; m < BM; m += NTHREADS) s_tok[m] = g_order[row0 + m];

    float acc[4][4][4];      // [m-frag 16][n-frag 8][quad] = 64 regs
#pragma unroll
    for (int a = 0; a < 4; a++)
#pragma unroll
        for (int b = 0; b < 4; b++)
#pragma unroll
            for (int c = 0; c < 4; c++) acc[a][b][c] = 0.f;

#pragma unroll
    for (int p = 0; p < PIPE - 1; p++) issue_stage(tid, sb, p, row0, e, col0, p * BK);

    // A ldsm (non-trans): lanes 0-15 -> rows, chunk = ks*2 + (lane>>4)
    int a_row = wm * 64 + (lane & 15);
    int a_cbit = (lane >> 4) & 1;
    // B ldsm.trans: lane -> k-row (lane&15), n-chunk-half (lane>>4)
    int b_krow = lane & 15;
    int b_chalf = lane >> 4;

    for (int s = 0; s < NKSTAGE; s++) {
        cp_wait<PIPE - 2>();
        __syncthreads();
        if (s + PIPE - 1 < NKSTAGE)
            issue_stage(tid, sb, s + PIPE - 1, row0, e, col0, (s + PIPE - 1) * BK);
        else
            cp_commit();   // keep wait_group accounting aligned

        uint32_t base = sb + (s % PIPE) * STAGE_BYTES;
        uint32_t bbase = base + B_OFF;

#pragma unroll
        for (int ks = 0; ks < 4; ks++) {        // 4 K-substeps of 16
            uint32_t a[4][4];
#pragma unroll
            for (int mf = 0; mf < 4; mf++)
                ldsm4(a[mf], base + A_OFF + swzA(a_row + mf * 16, ks * 2 + a_cbit));

            int krow = ks * 16 + b_krow;
#pragma unroll
            for (int t = 0; t < 2; t++) {
                // 16x16 region: k rows [ks*16,+16), cols wn*32 + t*16
                int cchunk = wn * 4 + t * 2 + b_chalf;
                uint32_t bh[4];
                ldsm4t(bh, bbase + swzB(krow, cchunk));
                // r0,r1 = cols +0..7 (k lo/hi); r2,r3 = cols +8..15
#pragma unroll
                for (int mf = 0; mf < 4; mf++) {
                    MMA(acc[mf][t * 2],     a[mf], bh[0], bh[1]);
                    MMA(acc[mf][t * 2 + 1], a[mf], bh[2], bh[3]);
                }
            }
        }
    }
    __syncthreads();

    // epilogue: add bias, scatter rows to original token positions
    const float* bias = eb + (size_t)e * D_FF + col0 + wn * 32;
#pragma unroll
    for (int mf = 0; mf < 4; mf++) {
        int r_lo = wm * 64 + mf * 16 + (lane >> 2);
        int t_lo = s_tok[r_lo];
        int t_hi = s_tok[r_lo + 8];
#pragma unroll
        for (int nf = 0; nf < 4; nf++) {
            int cb = nf * 8 + (lane & 3) * 2;
            float b0 = bias[cb], b1 = bias[cb + 1];
            if (t_lo >= 0) {
                float2 v = {acc[mf][nf][0] + b0, acc[mf][nf][1] + b1};
                *(float2*)(out + (size_t)t_lo * D_FF + col0 + wn * 32 + cb) = v;
            }
            if (t_hi >= 0) {
                float2 v = {acc[mf][nf][2] + b0, acc[mf][nf][3] + b1};
                *(float2*)(out + (size_t)t_hi * D_FF + col0 + wn * 32 + cb) = v;
            }
        }
    }
}

extern "C" void kernel_launch(void* const* d_in, const int* in_sizes, int n_in,
                              void* d_out, int out_size) {
    const float* x  = (const float*)d_in[0];
    const float* gw = (const float*)d_in[1];
    const float* gb = (const float*)d_in[2];
    const float* ew = (const float*)d_in[3];
    const float* eb = (const float*)d_in[4];
    float* out = (float*)d_out;

    cudaFuncSetAttribute(k_gemm, cudaFuncAttributeMaxDynamicSharedMemorySize, SMEM_TOTAL);

    k_init<<<(PAD_ROWS + 255) / 256, 256>>>();
    k_gate<<<N_TOKENS / 8, 256>>>(x, gw, gb);
    k_scan<<<1, 1>>>();
    k_scatter<<<N_TOKENS / 256, 256>>>();
    k_half_x<<<PAD_ROWS, 256>>>(x);
    k_whalf<<<(int)(((size_t)N_EXPERTS * D_MODEL * D_FF) / (256 * 8)), 256>>>(ew);
    {
        dim3 g(MAX_TILES, D_FF / BN);
        k_gemm<<<g, NTHREADS, SMEM_TOTAL>>>(eb, out);
    }
}